// round 1
// baseline (speedup 1.0000x reference)
#include <cuda_runtime.h>
#include <math.h>

// EdgeDecoder: p = sigmoid(ELU(ELU([src||dst] @ Wbi + bbi) @ W1 + b1) @ W2 + b2)
// for two edge types. fp32 baseline, register-tiled SIMT GEMM.

constexpr int Dm     = 128;     // embedding dim (= HID)
constexpr int TILE_E = 128;     // edges per block
constexpr int NTH    = 512;     // threads per block (16 warps)
constexpr int ESTR   = 260;     // padded row stride for edge tile (floats)
constexpr int SMEM_FLOATS = TILE_E * ESTR + 32 * 128 + 512;

__device__ __forceinline__ float elu1(float x) { return x > 0.f ? x : expm1f(x); }

__global__ __launch_bounds__(NTH, 1)
void edge_decoder_kernel(
    const float* __restrict__ user_emb, const float* __restrict__ item_emb,
    const void* __restrict__ ei_ui, const void* __restrict__ ei_iu,
    const float* __restrict__ Wbi_ui, const float* __restrict__ bbi_ui,
    const float* __restrict__ W1_ui,  const float* __restrict__ b1_ui,
    const float* __restrict__ W2_ui,  const float* __restrict__ b2_ui,
    const float* __restrict__ Wbi_iu, const float* __restrict__ bbi_iu,
    const float* __restrict__ W1_iu,  const float* __restrict__ b1_iu,
    const float* __restrict__ W2_iu,  const float* __restrict__ b2_iu,
    float* __restrict__ out, int E)
{
    extern __shared__ float sm[];
    float* sE    = sm;                      // [TILE_E][ESTR] gathered edge features, reused for h1
    float* sW    = sm + TILE_E * ESTR;      // [32][128] current weight K-chunk
    float* sBbi  = sW + 32 * 128;           // [128]
    float* sB1   = sBbi + 128;              // [128]
    float* sW2   = sB1 + 128;               // [128]
    float* sMisc = sW2 + 128;               // [0]=b2, [1]=is64 flag

    const int tid  = threadIdx.x;
    const int type = blockIdx.y;            // 0 = (user->item), 1 = (item->user)
    const int base = blockIdx.x * TILE_E;

    const float* srcE = type ? item_emb : user_emb;
    const float* dstE = type ? user_emb : item_emb;
    const void*  ei   = type ? ei_iu  : ei_ui;
    const float* Wbi  = type ? Wbi_iu : Wbi_ui;
    const float* bbi  = type ? bbi_iu : bbi_ui;
    const float* W1   = type ? W1_iu  : W1_ui;
    const float* b1   = type ? b1_iu  : b1_ui;
    const float* W2   = type ? W2_iu  : W2_ui;
    const float* b2   = type ? b2_iu  : b2_ui;

    if (tid < 128) {
        sBbi[tid] = bbi[tid];
        sB1[tid]  = b1[tid];
        sW2[tid]  = W2[tid];
    }
    if (tid == NTH - 1) {
        sMisc[0] = b2[0];
        // Detect index dtype: if int64, every odd 32-bit word (high half) is 0.
        // With int32 data the probability of 32 consecutive odd entries being 0 is ~0.
        const int* w = (const int*)ei_ui;
        int all0 = 1;
        #pragma unroll
        for (int k = 0; k < 32; k++) all0 &= (w[2 * k + 1] == 0);
        sMisc[1] = all0 ? 1.f : 0.f;
    }
    __syncthreads();
    const bool  is64 = (sMisc[1] != 0.f);
    const float b2v  = sMisc[0];

    // ---- Gather: sE[e][0:128] = srcE[idx0], sE[e][128:256] = dstE[idx1] ----
    #pragma unroll
    for (int it = 0; it < (TILE_E * 64) / NTH; it++) {
        int u   = tid + it * NTH;           // one float4 unit of the 256-float row
        int el  = u >> 6;                   // local edge
        int seg = u & 63;                   // float4 index within concat row
        int ge  = base + el;
        float4 v = make_float4(0.f, 0.f, 0.f, 0.f);
        if (ge < E) {
            int off = (seg < 32) ? ge : (E + ge);
            long long idx;
            if (is64) idx = ((const long long*)ei)[off];
            else      idx = (long long)((const int*)ei)[off];
            const float* row = (seg < 32 ? srcE : dstE) + (int)idx * Dm + (seg & 31) * 4;
            v = *(const float4*)row;
        }
        *(float4*)(sE + el * ESTR + seg * 4) = v;
    }
    __syncthreads();

    const int tx = tid & 31;                // hidden-col group (4 cols each)
    const int ty = tid >> 5;                // edge group (8 edges each)
    const int erow0 = ty * 8;

    // ---- GEMM1: h1[128e][128h] = E[128e][256] @ Wbi, +bias, ELU ----
    float acc[8][4];
    #pragma unroll
    for (int e = 0; e < 8; e++)
        acc[e][0] = acc[e][1] = acc[e][2] = acc[e][3] = 0.f;

    for (int kc = 0; kc < 2 * Dm; kc += 32) {
        #pragma unroll
        for (int i = tid; i < 1024; i += NTH) {     // stage 32x128 chunk (2 float4/thread)
            int r = i >> 5, c = (i & 31) * 4;
            *(float4*)(sW + r * 128 + c) = *(const float4*)(Wbi + (kc + r) * 128 + c);
        }
        __syncthreads();
        #pragma unroll 4
        for (int kk = 0; kk < 32; kk += 4) {
            float4 w0 = *(float4*)(sW + (kk + 0) * 128 + tx * 4);
            float4 w1 = *(float4*)(sW + (kk + 1) * 128 + tx * 4);
            float4 w2 = *(float4*)(sW + (kk + 2) * 128 + tx * 4);
            float4 w3 = *(float4*)(sW + (kk + 3) * 128 + tx * 4);
            #pragma unroll
            for (int e = 0; e < 8; e++) {
                float4 ev = *(float4*)(sE + (erow0 + e) * ESTR + kc + kk);
                acc[e][0] += ev.x * w0.x + ev.y * w1.x + ev.z * w2.x + ev.w * w3.x;
                acc[e][1] += ev.x * w0.y + ev.y * w1.y + ev.z * w2.y + ev.w * w3.y;
                acc[e][2] += ev.x * w0.z + ev.y * w1.z + ev.z * w2.z + ev.w * w3.z;
                acc[e][3] += ev.x * w0.w + ev.y * w1.w + ev.z * w2.w + ev.w * w3.w;
            }
        }
        __syncthreads();
    }

    // bias + ELU, store h1 back into sE (all GEMM1 reads completed at the sync above)
    #pragma unroll
    for (int e = 0; e < 8; e++) {
        float4 h;
        h.x = elu1(acc[e][0] + sBbi[tx * 4 + 0]);
        h.y = elu1(acc[e][1] + sBbi[tx * 4 + 1]);
        h.z = elu1(acc[e][2] + sBbi[tx * 4 + 2]);
        h.w = elu1(acc[e][3] + sBbi[tx * 4 + 3]);
        *(float4*)(sE + (erow0 + e) * ESTR + tx * 4) = h;
    }
    __syncthreads();

    // ---- GEMM2: h2 = ELU(h1 @ W1 + b1) ----
    float acc2[8][4];
    #pragma unroll
    for (int e = 0; e < 8; e++)
        acc2[e][0] = acc2[e][1] = acc2[e][2] = acc2[e][3] = 0.f;

    for (int kc = 0; kc < Dm; kc += 32) {
        #pragma unroll
        for (int i = tid; i < 1024; i += NTH) {
            int r = i >> 5, c = (i & 31) * 4;
            *(float4*)(sW + r * 128 + c) = *(const float4*)(W1 + (kc + r) * 128 + c);
        }
        __syncthreads();
        #pragma unroll 4
        for (int kk = 0; kk < 32; kk += 4) {
            float4 w0 = *(float4*)(sW + (kk + 0) * 128 + tx * 4);
            float4 w1 = *(float4*)(sW + (kk + 1) * 128 + tx * 4);
            float4 w2 = *(float4*)(sW + (kk + 2) * 128 + tx * 4);
            float4 w3 = *(float4*)(sW + (kk + 3) * 128 + tx * 4);
            #pragma unroll
            for (int e = 0; e < 8; e++) {
                float4 ev = *(float4*)(sE + (erow0 + e) * ESTR + kc + kk);
                acc2[e][0] += ev.x * w0.x + ev.y * w1.x + ev.z * w2.x + ev.w * w3.x;
                acc2[e][1] += ev.x * w0.y + ev.y * w1.y + ev.z * w2.y + ev.w * w3.y;
                acc2[e][2] += ev.x * w0.z + ev.y * w1.z + ev.z * w2.z + ev.w * w3.z;
                acc2[e][3] += ev.x * w0.w + ev.y * w1.w + ev.z * w2.w + ev.w * w3.w;
            }
        }
        __syncthreads();
    }

    // ---- Layer 3: partial dot with W2 (this thread's 4 cols), warp-reduce over tx ----
    float part[8];
    #pragma unroll
    for (int e = 0; e < 8; e++) {
        float s = 0.f;
        #pragma unroll
        for (int j = 0; j < 4; j++) {
            float h = elu1(acc2[e][j] + sB1[tx * 4 + j]);
            s += h * sW2[tx * 4 + j];
        }
        part[e] = s;
    }
    #pragma unroll
    for (int off = 16; off > 0; off >>= 1) {
        #pragma unroll
        for (int e = 0; e < 8; e++)
            part[e] += __shfl_xor_sync(0xffffffffu, part[e], off);
    }
    if (tx == 0) {
        #pragma unroll
        for (int e = 0; e < 8; e++) {
            int ge = base + erow0 + e;
            if (ge < E)
                out[(size_t)type * E + ge] = 1.f / (1.f + expf(-(part[e] + b2v)));
        }
    }
}

extern "C" void kernel_launch(void* const* d_in, const int* in_sizes, int n_in,
                              void* d_out, int out_size) {
    (void)n_in; (void)out_size;
    const int E = in_sizes[2] / 2;          // ei_ui has shape [2, E]
    size_t smem = SMEM_FLOATS * sizeof(float);
    cudaFuncSetAttribute(edge_decoder_kernel,
                         cudaFuncAttributeMaxDynamicSharedMemorySize, (int)smem);
    dim3 grid((E + TILE_E - 1) / TILE_E, 2);
    edge_decoder_kernel<<<grid, NTH, smem>>>(
        (const float*)d_in[0],  (const float*)d_in[1],
        d_in[2], d_in[3],
        (const float*)d_in[4],  (const float*)d_in[5],
        (const float*)d_in[6],  (const float*)d_in[7],
        (const float*)d_in[8],  (const float*)d_in[9],
        (const float*)d_in[10], (const float*)d_in[11],
        (const float*)d_in[12], (const float*)d_in[13],
        (const float*)d_in[14], (const float*)d_in[15],
        (float*)d_out, E);
}

// round 3
// speedup vs baseline: 1.8783x; 1.8783x over previous
#include <cuda_runtime.h>
#include <cuda_bf16.h>
#include <math.h>
#include <stdint.h>

// ============================================================================
// EdgeDecoder on HMMA (mma.sync m16n8k16 bf16, 3-term fp32-split emulation).
// p = sigmoid(ELU(ELU([src||dst]@Wbi+bbi)@W1+b1)@W2+b2), two edge types.
// ============================================================================

#define NTH 512

// ---- scratch: packed bf16 hi/lo weights in fragment order ----
__device__ uint32_t g_wbi_pack[65536];   // [type][chunk4][hl][ksic4][nt16][lane32][r2]
__device__ uint32_t g_w1_pack[32768];    // [type][chunk2][hl][ksic4][nt16][lane32][r2]

// ---- SMEM layout (bytes) ----
constexpr int OFF_A    = 0;        // A1 frags [hl2][mt8][ks16] * 528B = 135168 (A2 aliases)
constexpr int OFF_B    = 135168;   // 2 x 32768 B chunk buffers
constexpr int OFF_SOFF = 200704;   // u32[256] row offsets
constexpr int OFF_BBI  = 201728;   // float[128]
constexpr int OFF_B1   = 202240;
constexpr int OFF_W2   = 202752;
constexpr int OFF_PART = 203264;   // float[4][128]
constexpr int OFF_FLAG = 205312;   // [0]=b2, [1]=is64
constexpr int SMEM_TOTAL = 205568;

#define CPA(dst, src) \
    asm volatile("cp.async.cg.shared.global [%0], [%1], 16;" :: "r"(dst), "l"(src))
#define CPA_COMMIT() asm volatile("cp.async.commit_group;" ::: "memory")
#define CPA_WAIT(n)  asm volatile("cp.async.wait_group %0;" :: "n"(n) : "memory")

__device__ __forceinline__ uint32_t smem_to_u32(const void* p) {
    uint32_t a;
    asm("{ .reg .u64 t; cvta.to.shared.u64 t, %1; cvt.u32.u64 %0, t; }" : "=r"(a) : "l"(p));
    return a;
}

__device__ __forceinline__ void mma_bf16(float c[4], const uint32_t a[4], const uint32_t b[2]) {
    asm volatile(
        "mma.sync.aligned.m16n8k16.row.col.f32.bf16.bf16.f32 "
        "{%0,%1,%2,%3}, {%4,%5,%6,%7}, {%8,%9}, {%0,%1,%2,%3};"
        : "+f"(c[0]), "+f"(c[1]), "+f"(c[2]), "+f"(c[3])
        : "r"(a[0]), "r"(a[1]), "r"(a[2]), "r"(a[3]), "r"(b[0]), "r"(b[1]));
}

__device__ __forceinline__ float eluf(float x) { return x > 0.f ? x : (__expf(x) - 1.f); }

__device__ __forceinline__ void split_pack(float a, float b, uint32_t& hi, uint32_t& lo) {
    __nv_bfloat162 h = __float22bfloat162_rn(make_float2(a, b));
    float ra = a - __low2float(h);
    float rb = b - __high2float(h);
    __nv_bfloat162 l = __float22bfloat162_rn(make_float2(ra, rb));
    hi = *(uint32_t*)&h;
    lo = *(uint32_t*)&l;
}
__device__ __forceinline__ uint32_t pack_bf2(float a, float b) {
    __nv_bfloat162 h = __float22bfloat162_rn(make_float2(a, b));
    return *(uint32_t*)&h;
}

// ============================================================================
// Pre-pack kernel: fp32 weights -> bf16 hi/lo fragment-order arrays.
// Fragment (m16n8k16 B, row.col): b0 = {B[2t][g], B[2t+1][g]}, b1 = rows+8,
// where g = lane>>2, t = lane&3 and B[k][n] = W[k*128+n].
// ============================================================================
__global__ void pack_weights_kernel(
    const float* __restrict__ Wbi_ui, const float* __restrict__ W1_ui,
    const float* __restrict__ Wbi_iu, const float* __restrict__ W1_iu)
{
    int id = blockIdx.x * blockDim.x + threadIdx.x;
    const float* W;
    uint32_t* dst;
    int k, n, hl;
    if (id < 65536) {
        int r    = id & 1;
        int lane = (id >> 1) & 31;
        int nt   = (id >> 6) & 15;
        int ksic = (id >> 10) & 3;
        hl       = (id >> 12) & 1;
        int c    = (id >> 13) & 3;
        int type = (id >> 15) & 1;
        W = type ? Wbi_iu : Wbi_ui;
        k = (c * 4 + ksic) * 16 + (lane & 3) * 2 + r * 8;
        n = nt * 8 + (lane >> 2);
        dst = g_wbi_pack + id;
    } else {
        int id2 = id - 65536;
        if (id2 >= 32768) return;
        int r    = id2 & 1;
        int lane = (id2 >> 1) & 31;
        int nt   = (id2 >> 6) & 15;
        int ksic = (id2 >> 10) & 3;
        hl       = (id2 >> 12) & 1;
        int c    = (id2 >> 13) & 1;
        int type = (id2 >> 14) & 1;
        W = type ? W1_iu : W1_ui;
        k = (c * 4 + ksic) * 16 + (lane & 3) * 2 + r * 8;
        n = nt * 8 + (lane >> 2);
        dst = g_w1_pack + id2;
    }
    float v0 = W[k * 128 + n];
    float v1 = W[(k + 1) * 128 + n];
    __nv_bfloat162 h = __float22bfloat162_rn(make_float2(v0, v1));
    if (hl == 0) {
        *dst = *(uint32_t*)&h;
    } else {
        __nv_bfloat162 l = __float22bfloat162_rn(
            make_float2(v0 - __low2float(h), v1 - __high2float(h)));
        *dst = *(uint32_t*)&l;
    }
}

// ---- mma over one 4-kstep chunk ----
__device__ __forceinline__ void mma_chunk(
    const char* smA, const char* smB, int ksdim, int mi, int ni, int lane,
    int c, float C[2][4][4])
{
    const int perm16 = ((lane & 3) * 8 + (lane >> 2)) * 16;
    #pragma unroll
    for (int ksic = 0; ksic < 4; ksic++) {
        const int ks = c * 4 + ksic;
        uint4 A[2][2];
        #pragma unroll
        for (int mtl = 0; mtl < 2; mtl++)
            #pragma unroll
            for (int hl = 0; hl < 2; hl++) {
                const int mt = mi * 2 + mtl;
                A[mtl][hl] = *(const uint4*)(smA + ((hl * 8 + mt) * ksdim + ks) * 528 + perm16);
            }
        uint2 Bf[4][2];
        #pragma unroll
        for (int ntl = 0; ntl < 4; ntl++)
            #pragma unroll
            for (int hl = 0; hl < 2; hl++) {
                const int nt = ni * 4 + ntl;
                Bf[ntl][hl] = *(const uint2*)(smB + ((hl * 4 + ksic) * 16 + nt) * 256 + lane * 8);
            }
        // 3 split terms, 8 independent accumulation chains each
        #pragma unroll
        for (int mtl = 0; mtl < 2; mtl++)
            #pragma unroll
            for (int ntl = 0; ntl < 4; ntl++)
                mma_bf16(C[mtl][ntl], &A[mtl][0].x, &Bf[ntl][0].x);
        #pragma unroll
        for (int mtl = 0; mtl < 2; mtl++)
            #pragma unroll
            for (int ntl = 0; ntl < 4; ntl++)
                mma_bf16(C[mtl][ntl], &A[mtl][0].x, &Bf[ntl][1].x);
        #pragma unroll
        for (int mtl = 0; mtl < 2; mtl++)
            #pragma unroll
            for (int ntl = 0; ntl < 4; ntl++)
                mma_bf16(C[mtl][ntl], &A[mtl][1].x, &Bf[ntl][0].x);
    }
}

__device__ __forceinline__ void issue_chunk(
    uint32_t smB_u32, int s, const uint32_t* wbiP, const uint32_t* w1P, int tid)
{
    const uint32_t* src = (s < 4) ? (wbiP + (size_t)s * 8192)
                                  : (w1P + (size_t)(s - 4) * 8192);
    uint32_t dst = smB_u32 + (uint32_t)(s & 1) * 32768 + (uint32_t)tid * 16;
    #pragma unroll
    for (int j = 0; j < 4; j++)
        CPA(dst + j * 8192, src + tid * 4 + j * 2048);
    CPA_COMMIT();
}

__global__ __launch_bounds__(NTH, 1)
void edge_decoder_mma(
    const float* __restrict__ user_emb, const float* __restrict__ item_emb,
    const void* __restrict__ ei_ui, const void* __restrict__ ei_iu,
    const float* __restrict__ bbi_ui, const float* __restrict__ b1_ui,
    const float* __restrict__ W2_ui,  const float* __restrict__ b2_ui,
    const float* __restrict__ bbi_iu, const float* __restrict__ b1_iu,
    const float* __restrict__ W2_iu,  const float* __restrict__ b2_iu,
    float* __restrict__ out, int E)
{
    extern __shared__ char sm[];
    const uint32_t sm_u32 = smem_to_u32(sm);
    const int tid  = threadIdx.x;
    const int wid  = tid >> 5;
    const int lane = tid & 31;
    const int mi   = wid & 3;          // M-row group of this warp (32 rows)
    const int ni   = wid >> 2;         // N-col group (32 cols)
    const int g    = lane >> 2;
    const int t    = lane & 3;
    const int perm16 = ((lane & 3) * 8 + (lane >> 2)) * 16;

    constexpr int BPT = 74;
    const int type  = blockIdx.x / BPT;
    const int bslot = blockIdx.x % BPT;

    const float* srcE = type ? item_emb : user_emb;
    const float* dstE = type ? user_emb : item_emb;
    const void*  ei   = type ? ei_iu : ei_ui;
    const float* bbi  = type ? bbi_iu : bbi_ui;
    const float* b1   = type ? b1_iu : b1_ui;
    const float* W2   = type ? W2_iu : W2_ui;
    const float* b2   = type ? b2_iu : b2_ui;
    const uint32_t* wbiP = g_wbi_pack + (size_t)type * 32768;
    const uint32_t* w1P  = g_w1_pack  + (size_t)type * 16384;

    float*    sBbi  = (float*)(sm + OFF_BBI);
    float*    sB1   = (float*)(sm + OFF_B1);
    float*    sW2   = (float*)(sm + OFF_W2);
    float*    sPart = (float*)(sm + OFF_PART);
    float*    sFlag = (float*)(sm + OFF_FLAG);
    uint32_t* sOff  = (uint32_t*)(sm + OFF_SOFF);
    char*     smA   = sm + OFF_A;
    char*     smB   = sm + OFF_B;

    if (tid < 128) {
        sBbi[tid] = bbi[tid];
        sB1[tid]  = b1[tid];
        sW2[tid]  = W2[tid];
    }
    if (tid == NTH - 1) {
        sFlag[0] = b2[0];
        const int* w = (const int*)ei_ui;       // int64 detection
        int all0 = 1;
        #pragma unroll
        for (int k = 0; k < 32; k++) all0 &= (w[2 * k + 1] == 0);
        sFlag[1] = all0 ? 1.f : 0.f;
    }
    __syncthreads();
    const bool  is64 = (sFlag[1] != 0.f);
    const float b2v  = sFlag[0];

    const int ntiles = (E + 127) / 128;

    for (int tile = bslot; tile < ntiles; tile += BPT) {
        const int base = tile * 128;

        // ---- row offsets for this tile ----
        if (tid < 256) {
            const int half = tid >> 7, e = tid & 127, ge = base + e;
            uint32_t off = 0;
            if (ge < E) {
                long long idx = is64 ? ((const long long*)ei)[half ? (E + ge) : ge]
                                     : (long long)((const int*)ei)[half ? (E + ge) : ge];
                off = (uint32_t)idx << 7;
            }
            sOff[tid] = off;
        }
        issue_chunk(sm_u32 + OFF_B, 0, wbiP, w1P, tid);
        issue_chunk(sm_u32 + OFF_B, 1, wbiP, w1P, tid);
        __syncthreads();

        // ---- gather + split straight into A1 fragment layout ----
        #pragma unroll
        for (int i = 0; i < 8; i++) {
            const int v  = i * 16 + wid;        // (ks, mt) slot
            const int ks = v >> 3, mt = v & 7;
            const int half = ks >> 3;
            const int m0 = mt * 16 + g;
            const float* eb = half ? dstE : srcE;
            const uint32_t o0 = sOff[half * 128 + m0];
            const uint32_t o1 = sOff[half * 128 + m0 + 8];
            const int kf = (ks & 7) * 16 + 2 * t;
            float2 p00 = *(const float2*)(eb + o0 + kf);
            float2 p01 = *(const float2*)(eb + o0 + kf + 8);
            float2 p10 = *(const float2*)(eb + o1 + kf);
            float2 p11 = *(const float2*)(eb + o1 + kf + 8);
            uint4 hi, lo;
            split_pack(p00.x, p00.y, hi.x, lo.x);
            split_pack(p10.x, p10.y, hi.y, lo.y);
            split_pack(p01.x, p01.y, hi.z, lo.z);
            split_pack(p11.x, p11.y, hi.w, lo.w);
            *(uint4*)(smA + ((0 * 8 + mt) * 16 + ks) * 528 + perm16) = hi;
            *(uint4*)(smA + ((1 * 8 + mt) * 16 + ks) * 528 + perm16) = lo;
        }

        // ---- GEMM1: C1 = A1(128x256) @ Wbi, streamed B chunks ----
        float C[2][4][4];
        #pragma unroll
        for (int a = 0; a < 2; a++)
            #pragma unroll
            for (int b = 0; b < 4; b++)
                #pragma unroll
                for (int c = 0; c < 4; c++) C[a][b][c] = 0.f;

        #pragma unroll
        for (int s = 0; s < 4; s++) {
            CPA_WAIT(1);
            __syncthreads();
            mma_chunk(smA, smB + (s & 1) * 32768, 16, mi, ni, lane, s, C);
            __syncthreads();
            if (s + 2 <= 5) issue_chunk(sm_u32 + OFF_B, s + 2, wbiP, w1P, tid);
        }

        // ---- epilogue1: ELU(C1 + bbi) -> split -> A2 frags (alias A1) ----
        #pragma unroll
        for (int mtl = 0; mtl < 2; mtl++) {
            #pragma unroll
            for (int s = 0; s < 2; s++) {
                uint4 hi, lo;
                uint32_t* hp = &hi.x;
                uint32_t* lp = &lo.x;
                #pragma unroll
                for (int q = 0; q < 2; q++) {
                    const int ntl = 2 * s + q;
                    const int col = ni * 32 + ntl * 8 + 2 * t;
                    const float bb0 = sBbi[col], bb1 = sBbi[col + 1];
                    float h0 = eluf(C[mtl][ntl][0] + bb0);
                    float h1 = eluf(C[mtl][ntl][1] + bb1);
                    float h2 = eluf(C[mtl][ntl][2] + bb0);
                    float h3 = eluf(C[mtl][ntl][3] + bb1);
                    split_pack(h0, h1, hp[q * 2 + 0], lp[q * 2 + 0]);
                    split_pack(h2, h3, hp[q * 2 + 1], lp[q * 2 + 1]);
                }
                const int mt2 = mi * 2 + mtl, ks2 = ni * 2 + s;
                *(uint4*)(smA + ((0 * 8 + mt2) * 8 + ks2) * 528 + perm16) = hi;
                *(uint4*)(smA + ((1 * 8 + mt2) * 8 + ks2) * 528 + perm16) = lo;
            }
        }
        __syncthreads();

        // ---- GEMM2: C2 = A2(128x128) @ W1 ----
        #pragma unroll
        for (int a = 0; a < 2; a++)
            #pragma unroll
            for (int b = 0; b < 4; b++)
                #pragma unroll
                for (int c = 0; c < 4; c++) C[a][b][c] = 0.f;

        CPA_WAIT(1);
        __syncthreads();
        mma_chunk(smA, smB + (4 & 1) * 32768, 8, mi, ni, lane, 0, C);
        __syncthreads();
        CPA_WAIT(0);
        __syncthreads();
        mma_chunk(smA, smB + (5 & 1) * 32768, 8, mi, ni, lane, 1, C);
        __syncthreads();

        // ---- epilogue2: ELU(C2 + b1) . W2, reduce, sigmoid ----
        float r0[2] = {0.f, 0.f}, r1[2] = {0.f, 0.f};
        #pragma unroll
        for (int mtl = 0; mtl < 2; mtl++) {
            #pragma unroll
            for (int ntl = 0; ntl < 4; ntl++) {
                const int col = ni * 32 + ntl * 8 + 2 * t;
                const float w0 = sW2[col], w1 = sW2[col + 1];
                const float bb0 = sB1[col], bb1 = sB1[col + 1];
                r0[mtl] += eluf(C[mtl][ntl][0] + bb0) * w0 + eluf(C[mtl][ntl][1] + bb1) * w1;
                r1[mtl] += eluf(C[mtl][ntl][2] + bb0) * w0 + eluf(C[mtl][ntl][3] + bb1) * w1;
            }
        }
        #pragma unroll
        for (int off = 1; off <= 2; off <<= 1) {
            #pragma unroll
            for (int mtl = 0; mtl < 2; mtl++) {
                r0[mtl] += __shfl_xor_sync(0xffffffffu, r0[mtl], off);
                r1[mtl] += __shfl_xor_sync(0xffffffffu, r1[mtl], off);
            }
        }
        if (t == 0) {
            #pragma unroll
            for (int mtl = 0; mtl < 2; mtl++) {
                sPart[ni * 128 + mi * 32 + mtl * 16 + g]     = r0[mtl];
                sPart[ni * 128 + mi * 32 + mtl * 16 + g + 8] = r1[mtl];
            }
        }
        __syncthreads();
        if (tid < 128) {
            const int ge = base + tid;
            if (ge < E) {
                float s = sPart[tid] + sPart[128 + tid] + sPart[256 + tid]
                        + sPart[384 + tid] + b2v;
                out[(size_t)type * E + ge] = 1.f / (1.f + __expf(-s));
            }
        }
        __syncthreads();
    }
}

extern "C" void kernel_launch(void* const* d_in, const int* in_sizes, int n_in,
                              void* d_out, int out_size) {
    (void)n_in; (void)out_size;
    const int E = in_sizes[2] / 2;
    pack_weights_kernel<<<192, 512>>>(
        (const float*)d_in[4], (const float*)d_in[6],
        (const float*)d_in[10], (const float*)d_in[12]);
    cudaFuncSetAttribute(edge_decoder_mma,
                         cudaFuncAttributeMaxDynamicSharedMemorySize, SMEM_TOTAL);
    edge_decoder_mma<<<148, NTH, SMEM_TOTAL>>>(
        (const float*)d_in[0],  (const float*)d_in[1],
        d_in[2], d_in[3],
        (const float*)d_in[5],  (const float*)d_in[7],
        (const float*)d_in[8],  (const float*)d_in[9],
        (const float*)d_in[11], (const float*)d_in[13],
        (const float*)d_in[14], (const float*)d_in[15],
        (float*)d_out, E);
}

// round 4
// speedup vs baseline: 2.7169x; 1.4465x over previous
#include <cuda_runtime.h>
#include <cuda_bf16.h>
#include <math.h>
#include <stdint.h>

// ============================================================================
// EdgeDecoder on HMMA (mma.sync m16n8k16 bf16, 3-term fp32-split emulation).
// Round 4: Wbi resident in SMEM, A streamed in K-halves, W1 4-buffer stream,
// hi/lo-interleaved B frag lines (LDS.128), minimal syncs.
// ============================================================================

#define NTH 512

// packed bf16 hi/lo weights, fragment order:
// wbi: [type][ks16][nt16][lane32][q4]  (q: 0,1 = hi words; 2,3 = lo words)
__device__ __align__(128) uint32_t g_wbi_pack[65536];
// w1:  [type][ks8][nt16][lane32][q4]
__device__ __align__(128) uint32_t g_w1_pack[32768];

// ---- SMEM layout (bytes) ----
constexpr int OFF_A    = 0;        // A frags [hl2][mt8][ks8] * 512B = 65536 (sPart aliases)
constexpr int OFF_WBI  = 65536;    // resident Wbi frags: 16ks*16nt*512 = 131072
constexpr int OFF_W1S  = 196608;   // 4 x 8192 W1 stream buffers
constexpr int OFF_SOFF = 229376;   // u32[256]
constexpr int OFF_BBI  = 230400;   // float[128]
constexpr int OFF_B1   = 230912;
constexpr int OFF_W2   = 231424;
constexpr int OFF_FLAG = 231936;
constexpr int SMEM_TOTAL = 231968;

#define CPA(dst, src) \
    asm volatile("cp.async.cg.shared.global [%0], [%1], 16;" :: "r"(dst), "l"(src))
#define CPA_COMMIT() asm volatile("cp.async.commit_group;" ::: "memory")
#define CPA_WAIT(n)  asm volatile("cp.async.wait_group %0;" :: "n"(n) : "memory")

__device__ __forceinline__ uint32_t smem_to_u32(const void* p) {
    uint32_t a;
    asm("{ .reg .u64 t; cvta.to.shared.u64 t, %1; cvt.u32.u64 %0, t; }" : "=r"(a) : "l"(p));
    return a;
}

__device__ __forceinline__ void mma_bf16(float c[4], const uint32_t a[4], const uint32_t b[2]) {
    asm volatile(
        "mma.sync.aligned.m16n8k16.row.col.f32.bf16.bf16.f32 "
        "{%0,%1,%2,%3}, {%4,%5,%6,%7}, {%8,%9}, {%0,%1,%2,%3};"
        : "+f"(c[0]), "+f"(c[1]), "+f"(c[2]), "+f"(c[3])
        : "r"(a[0]), "r"(a[1]), "r"(a[2]), "r"(a[3]), "r"(b[0]), "r"(b[1]));
}

__device__ __forceinline__ float eluf(float x) { return x > 0.f ? x : (__expf(x) - 1.f); }

__device__ __forceinline__ void split_pack(float a, float b, uint32_t& hi, uint32_t& lo) {
    __nv_bfloat162 h = __float22bfloat162_rn(make_float2(a, b));
    float ra = a - __low2float(h);
    float rb = b - __high2float(h);
    __nv_bfloat162 l = __float22bfloat162_rn(make_float2(ra, rb));
    hi = *(uint32_t*)&h;
    lo = *(uint32_t*)&l;
}

// ============================================================================
// Pre-pack: fp32 weights -> frag-order lines, hi/lo interleaved per 16B line.
// B frag (m16n8k16, col): b_r = {B[k0+2t+r*8][n], B[k0+2t+1+r*8][n]}, n = nt*8+g.
// ============================================================================
__global__ void pack_weights_kernel(
    const float* __restrict__ Wbi_ui, const float* __restrict__ W1_ui,
    const float* __restrict__ Wbi_iu, const float* __restrict__ W1_iu)
{
    int id = blockIdx.x * blockDim.x + threadIdx.x;
    const float* W;
    uint32_t* dst;
    int ks, q, lane;
    if (id < 65536) {
        q    = id & 3;
        lane = (id >> 2) & 31;
        int nt   = (id >> 7) & 15;
        ks       = (id >> 11) & 15;
        int type = (id >> 15) & 1;
        W = type ? Wbi_iu : Wbi_ui;
        dst = g_wbi_pack + id;
        int r = q & 1;
        int k = ks * 16 + (lane & 3) * 2 + r * 8;
        int n = nt * 8 + (lane >> 2);
        float v0 = W[k * 128 + n], v1 = W[(k + 1) * 128 + n];
        __nv_bfloat162 h = __float22bfloat162_rn(make_float2(v0, v1));
        if (q < 2) { *dst = *(uint32_t*)&h; }
        else {
            __nv_bfloat162 l = __float22bfloat162_rn(
                make_float2(v0 - __low2float(h), v1 - __high2float(h)));
            *dst = *(uint32_t*)&l;
        }
    } else {
        int id2 = id - 65536;
        if (id2 >= 32768) return;
        q    = id2 & 3;
        lane = (id2 >> 2) & 31;
        int nt   = (id2 >> 7) & 15;
        ks       = (id2 >> 11) & 7;
        int type = (id2 >> 14) & 1;
        W = type ? W1_iu : W1_ui;
        dst = g_w1_pack + id2;
        int r = q & 1;
        int k = ks * 16 + (lane & 3) * 2 + r * 8;
        int n = nt * 8 + (lane >> 2);
        float v0 = W[k * 128 + n], v1 = W[(k + 1) * 128 + n];
        __nv_bfloat162 h = __float22bfloat162_rn(make_float2(v0, v1));
        if (q < 2) { *dst = *(uint32_t*)&h; }
        else {
            __nv_bfloat162 l = __float22bfloat162_rn(
                make_float2(v0 - __low2float(h), v1 - __high2float(h)));
            *dst = *(uint32_t*)&l;
        }
    }
}

// one ks step: 8 LDS.128 + 12 HMMA (3 split terms x 8 C tiles)
__device__ __forceinline__ void mma_step(
    const char* smA, const char* smBline, int ksl, int mi, int l16, float C[2][4][4])
{
    uint4 A[2][2];
    #pragma unroll
    for (int mtl = 0; mtl < 2; mtl++)
        #pragma unroll
        for (int hl = 0; hl < 2; hl++)
            A[mtl][hl] = *(const uint4*)(smA + ((hl * 8 + mi * 2 + mtl) * 8 + ksl) * 512 + l16);
    uint4 B[4];
    #pragma unroll
    for (int ntl = 0; ntl < 4; ntl++)
        B[ntl] = *(const uint4*)(smBline + ntl * 512 + l16);
    #pragma unroll
    for (int mtl = 0; mtl < 2; mtl++)
        #pragma unroll
        for (int ntl = 0; ntl < 4; ntl++)
            mma_bf16(C[mtl][ntl], &A[mtl][0].x, &B[ntl].x);   // hi*hi
    #pragma unroll
    for (int mtl = 0; mtl < 2; mtl++)
        #pragma unroll
        for (int ntl = 0; ntl < 4; ntl++)
            mma_bf16(C[mtl][ntl], &A[mtl][0].x, &B[ntl].z);   // hi*lo
    #pragma unroll
    for (int mtl = 0; mtl < 2; mtl++)
        #pragma unroll
        for (int ntl = 0; ntl < 4; ntl++)
            mma_bf16(C[mtl][ntl], &A[mtl][1].x, &B[ntl].x);   // lo*hi
}

__device__ __forceinline__ void gather_half(
    char* smA, const float* eb, const uint32_t* sOffH, int wid, int lane, int l16)
{
    const int g = lane >> 2, t = lane & 3;
    #pragma unroll
    for (int i = 0; i < 4; i++) {
        const int s = i * 16 + wid;
        const int mt = s & 7, ksl = s >> 3;
        const int m0 = mt * 16 + g;
        const uint32_t o0 = sOffH[m0], o1 = sOffH[m0 + 8];
        const int kf = ksl * 16 + 2 * t;
        float2 p00 = *(const float2*)(eb + o0 + kf);
        float2 p01 = *(const float2*)(eb + o0 + kf + 8);
        float2 p10 = *(const float2*)(eb + o1 + kf);
        float2 p11 = *(const float2*)(eb + o1 + kf + 8);
        uint4 hi, lo;
        split_pack(p00.x, p00.y, hi.x, lo.x);
        split_pack(p10.x, p10.y, hi.y, lo.y);
        split_pack(p01.x, p01.y, hi.z, lo.z);
        split_pack(p11.x, p11.y, hi.w, lo.w);
        *(uint4*)(smA + ((0 * 8 + mt) * 8 + ksl) * 512 + l16) = hi;
        *(uint4*)(smA + ((1 * 8 + mt) * 8 + ksl) * 512 + l16) = lo;
    }
}

__device__ __forceinline__ void issue_w1(uint32_t smW1S_u32, const uint32_t* w1P,
                                         int ks0, int tid)
{
    #pragma unroll
    for (int j = 0; j < 4; j++) {
        const int ks = ks0 + j;
        CPA(smW1S_u32 + (uint32_t)((ks & 3) * 8192 + tid * 16), w1P + ks * 2048 + tid * 4);
    }
    CPA_COMMIT();
}

__global__ __launch_bounds__(NTH, 1)
void edge_decoder_mma(
    const float* __restrict__ user_emb, const float* __restrict__ item_emb,
    const void* __restrict__ ei_ui, const void* __restrict__ ei_iu,
    const float* __restrict__ bbi_ui, const float* __restrict__ b1_ui,
    const float* __restrict__ W2_ui,  const float* __restrict__ b2_ui,
    const float* __restrict__ bbi_iu, const float* __restrict__ b1_iu,
    const float* __restrict__ W2_iu,  const float* __restrict__ b2_iu,
    float* __restrict__ out, int E)
{
    extern __shared__ char sm[];
    const uint32_t sm_u32 = smem_to_u32(sm);
    const int tid  = threadIdx.x;
    const int wid  = tid >> 5;
    const int lane = tid & 31;
    const int mi   = wid & 3;          // 32-row group
    const int ni   = wid >> 2;         // 32-col group
    const int g    = lane >> 2;
    const int t    = lane & 3;
    const int l16  = lane * 16;

    constexpr int BPT = 74;
    const int type  = blockIdx.x / BPT;
    const int bslot = blockIdx.x % BPT;

    const float* srcE = type ? item_emb : user_emb;
    const float* dstE = type ? user_emb : item_emb;
    const void*  ei   = type ? ei_iu : ei_ui;
    const float* bbi  = type ? bbi_iu : bbi_ui;
    const float* b1   = type ? b1_iu : b1_ui;
    const float* W2   = type ? W2_iu : W2_ui;
    const float* b2   = type ? b2_iu : b2_ui;
    const uint32_t* wbiP = g_wbi_pack + (size_t)type * 32768;
    const uint32_t* w1P  = g_w1_pack  + (size_t)type * 16384;

    float*    sBbi  = (float*)(sm + OFF_BBI);
    float*    sB1   = (float*)(sm + OFF_B1);
    float*    sW2   = (float*)(sm + OFF_W2);
    float*    sFlag = (float*)(sm + OFF_FLAG);
    uint32_t* sOff  = (uint32_t*)(sm + OFF_SOFF);
    char*     smA   = sm + OFF_A;
    char*     smWbi = sm + OFF_WBI;
    char*     smW1s = sm + OFF_W1S;
    float*    sPart = (float*)(sm + OFF_A);     // alias, used post-GEMM2

    if (tid < 128) {
        sBbi[tid] = bbi[tid];
        sB1[tid]  = b1[tid];
        sW2[tid]  = W2[tid];
    }
    if (tid == NTH - 1) {
        sFlag[0] = b2[0];
        const int* w = (const int*)ei_ui;       // int64 detection
        int all0 = 1;
        #pragma unroll
        for (int k = 0; k < 32; k++) all0 &= (w[2 * k + 1] == 0);
        sFlag[1] = all0 ? 1.f : 0.f;
    }

    // ---- one-time: load resident Wbi (hi/lo frag lines) ----
    {
        const uint32_t dstb = sm_u32 + OFF_WBI + (uint32_t)tid * 16;
        const uint32_t* src = wbiP + tid * 4;
        #pragma unroll
        for (int p = 0; p < 16; p++)
            CPA(dstb + (uint32_t)p * 8192, src + p * 2048);
        CPA_COMMIT();
        CPA_WAIT(0);
    }
    __syncthreads();
    const bool  is64 = (sFlag[1] != 0.f);
    const float b2v  = sFlag[0];

    const int ntiles = (E + 127) / 128;

    for (int tile = bslot; tile < ntiles; tile += BPT) {
        const int base = tile * 128;

        if (tid < 256) {
            const int half = tid >> 7, e = tid & 127, ge = base + e;
            uint32_t off = 0;
            if (ge < E) {
                long long idx = is64 ? ((const long long*)ei)[half ? (E + ge) : ge]
                                     : (long long)((const int*)ei)[half ? (E + ge) : ge];
                off = (uint32_t)idx << 7;
            }
            sOff[tid] = off;
        }
        __syncthreads();                                   // S1: sOff ready, sPart reads done

        // ---- gather src half -> A (K 0..127) ----
        gather_half(smA, srcE, sOff, wid, lane, l16);
        __syncthreads();                                   // S2

        // ---- GEMM1a: global ks 0..7 ----
        float C[2][4][4];
        #pragma unroll
        for (int a = 0; a < 2; a++)
            #pragma unroll
            for (int b = 0; b < 4; b++)
                #pragma unroll
                for (int c = 0; c < 4; c++) C[a][b][c] = 0.f;
        #pragma unroll
        for (int ks = 0; ks < 8; ks++)
            mma_step(smA, smWbi + (ks * 16 + ni * 4) * 512, ks, mi, l16, C);
        __syncthreads();                                   // S3: A consumed

        // ---- gather dst half -> A (K 128..255); prefetch W1 ks0-3 ----
        gather_half(smA, dstE, sOff + 128, wid, lane, l16);
        issue_w1(sm_u32 + OFF_W1S, w1P, 0, tid);
        __syncthreads();                                   // S4

        // ---- GEMM1b: global ks 8..15 ----
        #pragma unroll
        for (int ks = 8; ks < 16; ks++)
            mma_step(smA, smWbi + (ks * 16 + ni * 4) * 512, ks - 8, mi, l16, C);
        __syncthreads();                                   // S5: A consumed

        // ---- epilogue1: ELU(C+bbi) -> split -> A2 frag lines ----
        #pragma unroll
        for (int mtl = 0; mtl < 2; mtl++) {
            #pragma unroll
            for (int s = 0; s < 2; s++) {
                uint4 hi, lo;
                uint32_t* hp = &hi.x;
                uint32_t* lp = &lo.x;
                #pragma unroll
                for (int q = 0; q < 2; q++) {
                    const int ntl = 2 * s + q;
                    const int col = ni * 32 + ntl * 8 + 2 * t;
                    const float bb0 = sBbi[col], bb1 = sBbi[col + 1];
                    float h0 = eluf(C[mtl][ntl][0] + bb0);
                    float h1 = eluf(C[mtl][ntl][1] + bb1);
                    float h2 = eluf(C[mtl][ntl][2] + bb0);
                    float h3 = eluf(C[mtl][ntl][3] + bb1);
                    split_pack(h0, h1, hp[q * 2 + 0], lp[q * 2 + 0]);
                    split_pack(h2, h3, hp[q * 2 + 1], lp[q * 2 + 1]);
                }
                const int mt2 = mi * 2 + mtl, ks2 = ni * 2 + s;
                *(uint4*)(smA + ((0 * 8 + mt2) * 8 + ks2) * 512 + l16) = hi;
                *(uint4*)(smA + ((1 * 8 + mt2) * 8 + ks2) * 512 + l16) = lo;
            }
        }
        CPA_WAIT(0);
        __syncthreads();                                   // S6: A2 + W1 ks0-3 visible

        // ---- GEMM2: ks 0..3 from stream buffers ----
        #pragma unroll
        for (int a = 0; a < 2; a++)
            #pragma unroll
            for (int b = 0; b < 4; b++)
                #pragma unroll
                for (int c = 0; c < 4; c++) C[a][b][c] = 0.f;
        #pragma unroll
        for (int ks = 0; ks < 4; ks++)
            mma_step(smA, smW1s + (ks & 3) * 8192 + ni * 4 * 512, ks, mi, l16, C);
        __syncthreads();                                   // S7: buffers reusable

        issue_w1(sm_u32 + OFF_W1S, w1P, 4, tid);
        CPA_WAIT(0);
        __syncthreads();                                   // S8

        #pragma unroll
        for (int ks = 4; ks < 8; ks++)
            mma_step(smA, smW1s + (ks & 3) * 8192 + ni * 4 * 512, ks, mi, l16, C);
        __syncthreads();                                   // S9: A2 consumed -> sPart writable

        // ---- epilogue2: ELU(C+b1).W2, reduce, sigmoid ----
        float r0[2] = {0.f, 0.f}, r1[2] = {0.f, 0.f};
        #pragma unroll
        for (int mtl = 0; mtl < 2; mtl++) {
            #pragma unroll
            for (int ntl = 0; ntl < 4; ntl++) {
                const int col = ni * 32 + ntl * 8 + 2 * t;
                const float w0 = sW2[col], w1 = sW2[col + 1];
                const float bb0 = sB1[col], bb1 = sB1[col + 1];
                r0[mtl] += eluf(C[mtl][ntl][0] + bb0) * w0 + eluf(C[mtl][ntl][1] + bb1) * w1;
                r1[mtl] += eluf(C[mtl][ntl][2] + bb0) * w0 + eluf(C[mtl][ntl][3] + bb1) * w1;
            }
        }
        #pragma unroll
        for (int off = 1; off <= 2; off <<= 1) {
            #pragma unroll
            for (int mtl = 0; mtl < 2; mtl++) {
                r0[mtl] += __shfl_xor_sync(0xffffffffu, r0[mtl], off);
                r1[mtl] += __shfl_xor_sync(0xffffffffu, r1[mtl], off);
            }
        }
        if (t == 0) {
            #pragma unroll
            for (int mtl = 0; mtl < 2; mtl++) {
                sPart[ni * 128 + mi * 32 + mtl * 16 + g]     = r0[mtl];
                sPart[ni * 128 + mi * 32 + mtl * 16 + g + 8] = r1[mtl];
            }
        }
        __syncthreads();                                   // S10
        if (tid < 128) {
            const int ge = base + tid;
            if (ge < E) {
                float s = sPart[tid] + sPart[128 + tid] + sPart[256 + tid]
                        + sPart[384 + tid] + b2v;
                out[(size_t)type * E + ge] = 1.f / (1.f + __expf(-s));
            }
        }
        // next iteration's S1 protects sPart reads vs gather writes
    }
}

extern "C" void kernel_launch(void* const* d_in, const int* in_sizes, int n_in,
                              void* d_out, int out_size) {
    (void)n_in; (void)out_size;
    const int E = in_sizes[2] / 2;
    pack_weights_kernel<<<192, 512>>>(
        (const float*)d_in[4], (const float*)d_in[6],
        (const float*)d_in[10], (const float*)d_in[12]);
    cudaFuncSetAttribute(edge_decoder_mma,
                         cudaFuncAttributeMaxDynamicSharedMemorySize, SMEM_TOTAL);
    edge_decoder_mma<<<148, NTH, SMEM_TOTAL>>>(
        (const float*)d_in[0],  (const float*)d_in[1],
        d_in[2], d_in[3],
        (const float*)d_in[5],  (const float*)d_in[7],
        (const float*)d_in[8],  (const float*)d_in[9],
        (const float*)d_in[11], (const float*)d_in[13],
        (const float*)d_in[14], (const float*)d_in[15],
        (float*)d_out, E);
}

// round 5
// speedup vs baseline: 3.7590x; 1.3836x over previous
#include <cuda_runtime.h>
#include <cuda_fp16.h>
#include <math.h>
#include <stdint.h>

// ============================================================================
// EdgeDecoder, HMMA m16n8k16 fp16, 2-term fp32-split emulation (A hi/lo, B hi).
// 64-edge tiles, 256 thr/CTA, 2 CTAs/SM for cross-CTA tensor-pipe overlap.
// ============================================================================

#define NTH 256

// packed fp16 weights (hi only), fragment order:
// [type][ks][ntpair8][lane32][w4]  w: {nt_even b0, nt_even b1, nt_odd b0, nt_odd b1}
__device__ __align__(128) uint32_t g_wbi_pack[32768];   // 2 x 16ks x 8 x 32 x 4
__device__ __align__(128) uint32_t g_w1_pack[16384];    // 2 x 8ks  x 8 x 32 x 4

// ---- SMEM layout (bytes) ----
constexpr int OFF_A    = 0;        // A frags [hl2][mt4][ks16]*512 = 65536 (A2 aliases ks0..7)
constexpr int OFF_RING = 65536;    // 2 x 16384 weight chunk ring
constexpr int OFF_SOFF = 98304;    // u32[128]
constexpr int OFF_BBI  = 98816;    // f32[128]
constexpr int OFF_B1   = 99328;
constexpr int OFF_W2   = 99840;
constexpr int OFF_PART = 100352;   // f32[128]
constexpr int SMEM_TOTAL = 100864;

#define CPA(dst, src) \
    asm volatile("cp.async.cg.shared.global [%0], [%1], 16;" :: "r"(dst), "l"(src))
#define CPA_COMMIT() asm volatile("cp.async.commit_group;" ::: "memory")
#define CPA_WAIT(n)  asm volatile("cp.async.wait_group %0;" :: "n"(n) : "memory")

__device__ __forceinline__ uint32_t smem_to_u32(const void* p) {
    uint32_t a;
    asm("{ .reg .u64 t; cvta.to.shared.u64 t, %1; cvt.u32.u64 %0, t; }" : "=r"(a) : "l"(p));
    return a;
}

__device__ __forceinline__ void mma_f16(float c[4], const uint32_t a[4],
                                        uint32_t b0, uint32_t b1) {
    asm volatile(
        "mma.sync.aligned.m16n8k16.row.col.f32.f16.f16.f32 "
        "{%0,%1,%2,%3}, {%4,%5,%6,%7}, {%8,%9}, {%0,%1,%2,%3};"
        : "+f"(c[0]), "+f"(c[1]), "+f"(c[2]), "+f"(c[3])
        : "r"(a[0]), "r"(a[1]), "r"(a[2]), "r"(a[3]), "r"(b0), "r"(b1));
}

__device__ __forceinline__ float eluf(float x) { return x > 0.f ? x : (__expf(x) - 1.f); }

__device__ __forceinline__ void split_pack_h(float a, float b, uint32_t& hi, uint32_t& lo) {
    __half2 h = __floats2half2_rn(a, b);
    float2 hf = __half22float2(h);
    __half2 l = __floats2half2_rn(a - hf.x, b - hf.y);
    hi = *(uint32_t*)&h;
    lo = *(uint32_t*)&l;
}

// ============================================================================
// Pre-pack: fp32 weights -> fp16 (hi) frag-order lines, 2 nt per 16B line.
// B frag (m16n8k16 col): b_r = {W[k0+2t+8r][n], W[k0+2t+1+8r][n]}, n = nt*8+g.
// ============================================================================
__global__ void pack_weights_kernel(
    const float* __restrict__ Wbi_ui, const float* __restrict__ W1_ui,
    const float* __restrict__ Wbi_iu, const float* __restrict__ W1_iu)
{
    int id = blockIdx.x * blockDim.x + threadIdx.x;
    const float* W;
    uint32_t* dst;
    int w, lane, ntp, ks;
    if (id < 32768) {
        w = id & 3; lane = (id >> 2) & 31; ntp = (id >> 7) & 7;
        ks = (id >> 10) & 15;
        int type = (id >> 14) & 1;
        W = type ? Wbi_iu : Wbi_ui;
        dst = g_wbi_pack + id;
    } else {
        int id2 = id - 32768;
        if (id2 >= 16384) return;
        w = id2 & 3; lane = (id2 >> 2) & 31; ntp = (id2 >> 7) & 7;
        ks = (id2 >> 10) & 7;
        int type = (id2 >> 13) & 1;
        W = type ? W1_iu : W1_ui;
        dst = g_w1_pack + id2;
    }
    int nt = ntp * 2 + (w >> 1), r = w & 1;
    int k = ks * 16 + (lane & 3) * 2 + r * 8;
    int n = nt * 8 + (lane >> 2);
    __half2 h = __floats2half2_rn(W[k * 128 + n], W[(k + 1) * 128 + n]);
    *dst = *(uint32_t*)&h;
}

// one ks step for one warp: 2 A LDS.128 + 4 B LDS.128 + 16 HMMA
__device__ __forceinline__ void mma_step(
    const char* smA, const char* smB_ks, int ks_a, int mi, int ni, int l16, float C[8][4])
{
    uint4 Ah = *(const uint4*)(smA + ((0 * 4 + mi) * 16 + ks_a) * 512 + l16);
    uint4 Al = *(const uint4*)(smA + ((1 * 4 + mi) * 16 + ks_a) * 512 + l16);
    #pragma unroll
    for (int p = 0; p < 4; p++) {
        uint4 B = *(const uint4*)(smB_ks + (ni * 4 + p) * 512 + l16);
        mma_f16(C[2 * p],     &Ah.x, B.x, B.y);
        mma_f16(C[2 * p],     &Al.x, B.x, B.y);
        mma_f16(C[2 * p + 1], &Ah.x, B.z, B.w);
        mma_f16(C[2 * p + 1], &Al.x, B.z, B.w);
    }
}

__device__ __forceinline__ void issue_chunk(
    uint32_t ring_u32, int c, const uint32_t* wbiP, const uint32_t* w1P, int tid)
{
    const uint32_t* src = (c < 4) ? (wbiP + c * 4096) : (w1P + (c - 4) * 4096);
    uint32_t dst = ring_u32 + (uint32_t)(c & 1) * 16384;
    #pragma unroll
    for (int q = 0; q < 4; q++)
        CPA(dst + (uint32_t)(tid + q * 256) * 16, src + (tid + q * 256) * 4);
    CPA_COMMIT();
}

__global__ __launch_bounds__(NTH, 2)
void edge_decoder_mma(
    const float* __restrict__ user_emb, const float* __restrict__ item_emb,
    const void* __restrict__ ei_ui, const void* __restrict__ ei_iu,
    const float* __restrict__ bbi_ui, const float* __restrict__ b1_ui,
    const float* __restrict__ W2_ui,  const float* __restrict__ b2_ui,
    const float* __restrict__ bbi_iu, const float* __restrict__ b1_iu,
    const float* __restrict__ W2_iu,  const float* __restrict__ b2_iu,
    float* __restrict__ out, int E)
{
    extern __shared__ char sm[];
    const uint32_t sm_u32 = smem_to_u32(sm);
    const int tid  = threadIdx.x;
    const int wid  = tid >> 5;
    const int lane = tid & 31;
    const int mi   = wid & 3;           // 16-row group
    const int ni   = wid >> 2;          // 64-col group (0..1)
    const int g    = lane >> 2;
    const int t    = lane & 3;
    const int l16  = lane * 16;

    const int type = blockIdx.y;
    const int base = blockIdx.x * 64;

    const float* srcE = type ? item_emb : user_emb;
    const float* dstE = type ? user_emb : item_emb;
    const void*  ei   = type ? ei_iu : ei_ui;
    const float* bbi  = type ? bbi_iu : bbi_ui;
    const float* b1   = type ? b1_iu : b1_ui;
    const float* W2   = type ? W2_iu : W2_ui;
    const float* b2   = type ? b2_iu : b2_ui;
    const uint32_t* wbiP = g_wbi_pack + (size_t)type * 16384;
    const uint32_t* w1P  = g_w1_pack  + (size_t)type * 8192;

    float*    sBbi  = (float*)(sm + OFF_BBI);
    float*    sB1   = (float*)(sm + OFF_B1);
    float*    sW2   = (float*)(sm + OFF_W2);
    float*    sPart = (float*)(sm + OFF_PART);
    uint32_t* sOff  = (uint32_t*)(sm + OFF_SOFF);
    char*     smA   = sm + OFF_A;
    char*     smRing = sm + OFF_RING;

    // start weight stream immediately (chunks 0,1)
    issue_chunk(sm_u32 + OFF_RING, 0, wbiP, w1P, tid);
    issue_chunk(sm_u32 + OFF_RING, 1, wbiP, w1P, tid);

    // int64-index detection, per-thread (broadcast L2 reads; certainty 1-1e-40)
    bool is64;
    {
        const int* w = (const int*)ei_ui;
        int all0 = 1;
        #pragma unroll
        for (int k = 0; k < 8; k++) all0 &= (w[2 * k + 1] == 0);
        is64 = (all0 != 0);
    }
    const float b2v = b2[0];

    if (tid < 128) {
        sBbi[tid] = bbi[tid];
        sB1[tid]  = b1[tid];
        sW2[tid]  = W2[tid];
        // row offsets: [0..63] src, [64..127] dst (float index, rows <<7)
        const int half = tid >> 6, e = tid & 63, ge = base + e;
        uint32_t off = 0;
        if (ge < E) {
            long long idx = is64 ? ((const long long*)ei)[half ? (E + ge) : ge]
                                 : (long long)((const int*)ei)[half ? (E + ge) : ge];
            off = (uint32_t)idx << 7;
        }
        sOff[tid] = off;
    }
    __syncthreads();                                   // B1: sOff/bias ready

    // ---- gather full-K into A1 frag lines (warp-per-slot, 64 slots) ----
    #pragma unroll
    for (int i = 0; i < 8; i++) {
        const int s  = i * 8 + wid;
        const int mt = s & 3, ks = s >> 2;
        const int half = ks >> 3;
        const float* eb = half ? dstE : srcE;
        const int m0 = mt * 16 + g;
        const uint32_t o0 = sOff[half * 64 + m0];
        const uint32_t o1 = sOff[half * 64 + m0 + 8];
        const int kf = (ks & 7) * 16 + 2 * t;
        float2 p00 = *(const float2*)(eb + o0 + kf);
        float2 p01 = *(const float2*)(eb + o0 + kf + 8);
        float2 p10 = *(const float2*)(eb + o1 + kf);
        float2 p11 = *(const float2*)(eb + o1 + kf + 8);
        uint4 hi, lo;
        split_pack_h(p00.x, p00.y, hi.x, lo.x);
        split_pack_h(p10.x, p10.y, hi.y, lo.y);
        split_pack_h(p01.x, p01.y, hi.z, lo.z);
        split_pack_h(p11.x, p11.y, hi.w, lo.w);
        *(uint4*)(smA + ((0 * 4 + mt) * 16 + ks) * 512 + l16) = hi;
        *(uint4*)(smA + ((1 * 4 + mt) * 16 + ks) * 512 + l16) = lo;
    }
    __syncthreads();                                   // B2: A1 ready

    // ---- GEMM1: 4 chunks x 4 ks, ring-streamed Wbi ----
    float C[8][4];
    #pragma unroll
    for (int a = 0; a < 8; a++)
        #pragma unroll
        for (int b = 0; b < 4; b++) C[a][b] = 0.f;

    #pragma unroll
    for (int c = 0; c < 4; c++) {
        CPA_WAIT(1);
        __syncthreads();                               // chunk c visible
        const char* bb = smRing + (c & 1) * 16384;
        #pragma unroll
        for (int klc = 0; klc < 4; klc++)
            mma_step(smA, bb + klc * 4096, c * 4 + klc, mi, ni, l16, C);
        __syncthreads();                               // buf (c&1) reusable
        issue_chunk(sm_u32 + OFF_RING, c + 2, wbiP, w1P, tid);
    }

    // ---- epilogue1: ELU(C+bbi) -> fp16 split -> A2 frag lines (ks 0..7) ----
    #pragma unroll
    for (int s = 0; s < 4; s++) {
        uint4 hi, lo;
        int col = ni * 64 + (2 * s) * 8 + 2 * t;
        {
            const float bb0 = sBbi[col], bb1 = sBbi[col + 1];
            float h0 = eluf(C[2 * s][0] + bb0);
            float h1 = eluf(C[2 * s][1] + bb1);
            float h2 = eluf(C[2 * s][2] + bb0);
            float h3 = eluf(C[2 * s][3] + bb1);
            split_pack_h(h0, h1, hi.x, lo.x);
            split_pack_h(h2, h3, hi.y, lo.y);
        }
        col += 8;
        {
            const float bb0 = sBbi[col], bb1 = sBbi[col + 1];
            float h0 = eluf(C[2 * s + 1][0] + bb0);
            float h1 = eluf(C[2 * s + 1][1] + bb1);
            float h2 = eluf(C[2 * s + 1][2] + bb0);
            float h3 = eluf(C[2 * s + 1][3] + bb1);
            split_pack_h(h0, h1, hi.z, lo.z);
            split_pack_h(h2, h3, hi.w, lo.w);
        }
        const int ks2 = ni * 4 + s;
        *(uint4*)(smA + ((0 * 4 + mi) * 16 + ks2) * 512 + l16) = hi;
        *(uint4*)(smA + ((1 * 4 + mi) * 16 + ks2) * 512 + l16) = lo;
    }

    // ---- GEMM2: chunks 4,5 (W1) ----
    float C2[8][4];
    #pragma unroll
    for (int a = 0; a < 8; a++)
        #pragma unroll
        for (int b = 0; b < 4; b++) C2[a][b] = 0.f;

    CPA_WAIT(1);
    __syncthreads();                                   // chunk 4 + A2 visible
    {
        const char* bb = smRing + (4 & 1) * 16384;
        #pragma unroll
        for (int klc = 0; klc < 4; klc++)
            mma_step(smA, bb + klc * 4096, klc, mi, ni, l16, C2);
    }
    CPA_WAIT(0);
    __syncthreads();                                   // chunk 5 visible
    {
        const char* bb = smRing + (5 & 1) * 16384;
        #pragma unroll
        for (int klc = 0; klc < 4; klc++)
            mma_step(smA, bb + klc * 4096, 4 + klc, mi, ni, l16, C2);
    }

    // ---- epilogue2: ELU(C2+b1) . W2, quad-shuffle reduce, sigmoid ----
    float r0 = 0.f, r1 = 0.f;
    #pragma unroll
    for (int ntl = 0; ntl < 8; ntl++) {
        const int col = ni * 64 + ntl * 8 + 2 * t;
        const float w0 = sW2[col], w1 = sW2[col + 1];
        const float bb0 = sB1[col], bb1 = sB1[col + 1];
        r0 += eluf(C2[ntl][0] + bb0) * w0 + eluf(C2[ntl][1] + bb1) * w1;
        r1 += eluf(C2[ntl][2] + bb0) * w0 + eluf(C2[ntl][3] + bb1) * w1;
    }
    r0 += __shfl_xor_sync(0xffffffffu, r0, 1);
    r1 += __shfl_xor_sync(0xffffffffu, r1, 1);
    r0 += __shfl_xor_sync(0xffffffffu, r0, 2);
    r1 += __shfl_xor_sync(0xffffffffu, r1, 2);
    if (t == 0) {
        sPart[ni * 64 + mi * 16 + g]     = r0;
        sPart[ni * 64 + mi * 16 + g + 8] = r1;
    }
    __syncthreads();
    if (tid < 64) {
        const int ge = base + tid;
        if (ge < E) {
            float s = sPart[tid] + sPart[64 + tid] + b2v;
            out[(size_t)type * E + ge] = 1.f / (1.f + __expf(-s));
        }
    }
}

extern "C" void kernel_launch(void* const* d_in, const int* in_sizes, int n_in,
                              void* d_out, int out_size) {
    (void)n_in; (void)out_size;
    const int E = in_sizes[2] / 2;
    pack_weights_kernel<<<96, 512>>>(
        (const float*)d_in[4], (const float*)d_in[6],
        (const float*)d_in[10], (const float*)d_in[12]);
    cudaFuncSetAttribute(edge_decoder_mma,
                         cudaFuncAttributeMaxDynamicSharedMemorySize, SMEM_TOTAL);
    dim3 grid((E + 63) / 64, 2);
    edge_decoder_mma<<<grid, NTH, SMEM_TOTAL>>>(
        (const float*)d_in[0],  (const float*)d_in[1],
        d_in[2], d_in[3],
        (const float*)d_in[5],  (const float*)d_in[7],
        (const float*)d_in[8],  (const float*)d_in[9],
        (const float*)d_in[11], (const float*)d_in[13],
        (const float*)d_in[14], (const float*)d_in[15],
        (float*)d_out, E);
}

// round 6
// speedup vs baseline: 5.5571x; 1.4783x over previous
#include <cuda_runtime.h>
#include <cuda_fp16.h>
#include <math.h>
#include <stdint.h>

// ============================================================================
// EdgeDecoder, HMMA m16n8k16 fp16 single-term (fp32 accum).
// 128-edge tiles, 256 thr/CTA, 2 CTAs/SM. Weights streamed via 2x16KB ring.
// ============================================================================

#define NTH 256

// packed fp16 weights (hi only), fragment order:
// [type][ks][ntpair8][lane32][w4]  w: {nt_even b0, nt_even b1, nt_odd b0, nt_odd b1}
__device__ __align__(128) uint32_t g_wbi_pack[32768];   // 2 x 16ks x 8 x 32 x 4
__device__ __align__(128) uint32_t g_w1_pack[16384];    // 2 x 8ks  x 8 x 32 x 4

// ---- SMEM layout (bytes) ----
constexpr int OFF_A    = 0;        // A frags [mt8][ks16]*512 = 65536 (A2 aliases ks0..7)
constexpr int OFF_RING = 65536;    // 2 x 16384 weight chunk ring
constexpr int OFF_SOFF = 98304;    // u32[256]
constexpr int OFF_BBI  = 99328;    // f32[128]
constexpr int OFF_B1   = 99840;
constexpr int OFF_W2   = 100352;
constexpr int OFF_PART = 100864;   // f32[256]
constexpr int SMEM_TOTAL = 101888;

#define CPA(dst, src) \
    asm volatile("cp.async.cg.shared.global [%0], [%1], 16;" :: "r"(dst), "l"(src))
#define CPA_COMMIT() asm volatile("cp.async.commit_group;" ::: "memory")
#define CPA_WAIT(n)  asm volatile("cp.async.wait_group %0;" :: "n"(n) : "memory")

__device__ __forceinline__ uint32_t smem_to_u32(const void* p) {
    uint32_t a;
    asm("{ .reg .u64 t; cvta.to.shared.u64 t, %1; cvt.u32.u64 %0, t; }" : "=r"(a) : "l"(p));
    return a;
}

__device__ __forceinline__ void mma_f16(float c[4], const uint32_t a[4],
                                        uint32_t b0, uint32_t b1) {
    asm volatile(
        "mma.sync.aligned.m16n8k16.row.col.f32.f16.f16.f32 "
        "{%0,%1,%2,%3}, {%4,%5,%6,%7}, {%8,%9}, {%0,%1,%2,%3};"
        : "+f"(c[0]), "+f"(c[1]), "+f"(c[2]), "+f"(c[3])
        : "r"(a[0]), "r"(a[1]), "r"(a[2]), "r"(a[3]), "r"(b0), "r"(b1));
}

__device__ __forceinline__ float eluf(float x) { return x > 0.f ? x : (__expf(x) - 1.f); }

__device__ __forceinline__ uint32_t pack_h2(float a, float b) {
    __half2 h = __floats2half2_rn(a, b);
    return *(uint32_t*)&h;
}

// ============================================================================
// Pre-pack: fp32 weights -> fp16 frag-order lines, 2 nt per 16B line.
// B frag (m16n8k16 col): b_r = {W[k0+2t+8r][n], W[k0+2t+1+8r][n]}, n = nt*8+g.
// ============================================================================
__global__ void pack_weights_kernel(
    const float* __restrict__ Wbi_ui, const float* __restrict__ W1_ui,
    const float* __restrict__ Wbi_iu, const float* __restrict__ W1_iu)
{
    int id = blockIdx.x * blockDim.x + threadIdx.x;
    const float* W;
    uint32_t* dst;
    int w, lane, ntp, ks;
    if (id < 32768) {
        w = id & 3; lane = (id >> 2) & 31; ntp = (id >> 7) & 7;
        ks = (id >> 10) & 15;
        int type = (id >> 14) & 1;
        W = type ? Wbi_iu : Wbi_ui;
        dst = g_wbi_pack + id;
    } else {
        int id2 = id - 32768;
        if (id2 >= 16384) return;
        w = id2 & 3; lane = (id2 >> 2) & 31; ntp = (id2 >> 7) & 7;
        ks = (id2 >> 10) & 7;
        int type = (id2 >> 13) & 1;
        W = type ? W1_iu : W1_ui;
        dst = g_w1_pack + id2;
    }
    int nt = ntp * 2 + (w >> 1), r = w & 1;
    int k = ks * 16 + (lane & 3) * 2 + r * 8;
    int n = nt * 8 + (lane >> 2);
    *dst = pack_h2(W[k * 128 + n], W[(k + 1) * 128 + n]);
}

// one ks step for one warp: 2 A LDS.128 + 4 B LDS.128 + 16 HMMA
__device__ __forceinline__ void mma_step(
    const char* smA, const char* smB_ks, int ks_a, int mi, int ni, int l16,
    float C[2][8][4])
{
    uint4 A0 = *(const uint4*)(smA + ((mi * 2 + 0) * 16 + ks_a) * 512 + l16);
    uint4 A1 = *(const uint4*)(smA + ((mi * 2 + 1) * 16 + ks_a) * 512 + l16);
    #pragma unroll
    for (int p = 0; p < 4; p++) {
        uint4 B = *(const uint4*)(smB_ks + (ni * 4 + p) * 512 + l16);
        mma_f16(C[0][2 * p],     &A0.x, B.x, B.y);
        mma_f16(C[1][2 * p],     &A1.x, B.x, B.y);
        mma_f16(C[0][2 * p + 1], &A0.x, B.z, B.w);
        mma_f16(C[1][2 * p + 1], &A1.x, B.z, B.w);
    }
}

__device__ __forceinline__ void issue_chunk(
    uint32_t ring_u32, int c, const uint32_t* wbiP, const uint32_t* w1P, int tid)
{
    const uint32_t* src = (c < 4) ? (wbiP + c * 4096) : (w1P + (c - 4) * 4096);
    uint32_t dst = ring_u32 + (uint32_t)(c & 1) * 16384;
    #pragma unroll
    for (int q = 0; q < 4; q++)
        CPA(dst + (uint32_t)(tid + q * 256) * 16, src + (tid + q * 256) * 4);
    CPA_COMMIT();
}

__global__ __launch_bounds__(NTH, 2)
void edge_decoder_mma(
    const float* __restrict__ user_emb, const float* __restrict__ item_emb,
    const void* __restrict__ ei_ui, const void* __restrict__ ei_iu,
    const float* __restrict__ bbi_ui, const float* __restrict__ b1_ui,
    const float* __restrict__ W2_ui,  const float* __restrict__ b2_ui,
    const float* __restrict__ bbi_iu, const float* __restrict__ b1_iu,
    const float* __restrict__ W2_iu,  const float* __restrict__ b2_iu,
    float* __restrict__ out, int E)
{
    extern __shared__ char sm[];
    const uint32_t sm_u32 = smem_to_u32(sm);
    const int tid  = threadIdx.x;
    const int wid  = tid >> 5;
    const int lane = tid & 31;
    const int mi   = wid & 3;           // 32-row group (2 m16 tiles)
    const int ni   = wid >> 2;          // 64-col group (0..1)
    const int g    = lane >> 2;
    const int t    = lane & 3;
    const int l16  = lane * 16;

    const int type = blockIdx.y;
    const int base = blockIdx.x * 128;

    const float* srcE = type ? item_emb : user_emb;
    const float* dstE = type ? user_emb : item_emb;
    const void*  ei   = type ? ei_iu : ei_ui;
    const float* bbi  = type ? bbi_iu : bbi_ui;
    const float* b1   = type ? b1_iu : b1_ui;
    const float* W2   = type ? W2_iu : W2_ui;
    const float* b2   = type ? b2_iu : b2_ui;
    const uint32_t* wbiP = g_wbi_pack + (size_t)type * 16384;
    const uint32_t* w1P  = g_w1_pack  + (size_t)type * 8192;

    float*    sBbi  = (float*)(sm + OFF_BBI);
    float*    sB1   = (float*)(sm + OFF_B1);
    float*    sW2   = (float*)(sm + OFF_W2);
    float*    sPart = (float*)(sm + OFF_PART);
    uint32_t* sOff  = (uint32_t*)(sm + OFF_SOFF);
    char*     smA   = sm + OFF_A;
    char*     smRing = sm + OFF_RING;

    // start weight stream immediately (chunks 0,1)
    issue_chunk(sm_u32 + OFF_RING, 0, wbiP, w1P, tid);
    issue_chunk(sm_u32 + OFF_RING, 1, wbiP, w1P, tid);

    // int64-index detection (broadcast L2 reads)
    bool is64;
    {
        const int* w = (const int*)ei_ui;
        int all0 = 1;
        #pragma unroll
        for (int k = 0; k < 8; k++) all0 &= (w[2 * k + 1] == 0);
        is64 = (all0 != 0);
    }
    const float b2v = b2[0];

    if (tid < 128) {
        sBbi[tid] = bbi[tid];
        sB1[tid]  = b1[tid];
        sW2[tid]  = W2[tid];
    }
    // row offsets: [0..127] src, [128..255] dst
    {
        const int half = tid >> 7, e = tid & 127, ge = base + e;
        uint32_t off = 0;
        if (ge < E) {
            long long idx = is64 ? ((const long long*)ei)[half ? (E + ge) : ge]
                                 : (long long)((const int*)ei)[half ? (E + ge) : ge];
            off = (uint32_t)idx << 7;
        }
        sOff[tid] = off;
    }
    __syncthreads();                                   // B1: sOff/bias ready

    // ---- gather full-K into A1 frag lines (128 slots: mt8 x ks16) ----
    #pragma unroll
    for (int i = 0; i < 16; i++) {
        const int s  = i * 8 + wid;
        const int mt = s & 7, ks = s >> 3;
        const int half = ks >> 3;
        const float* eb = half ? dstE : srcE;
        const int m0 = mt * 16 + g;
        const uint32_t o0 = sOff[half * 128 + m0];
        const uint32_t o1 = sOff[half * 128 + m0 + 8];
        const int kf = (ks & 7) * 16 + 2 * t;
        float2 p00 = *(const float2*)(eb + o0 + kf);
        float2 p01 = *(const float2*)(eb + o0 + kf + 8);
        float2 p10 = *(const float2*)(eb + o1 + kf);
        float2 p11 = *(const float2*)(eb + o1 + kf + 8);
        uint4 hi;
        hi.x = pack_h2(p00.x, p00.y);
        hi.y = pack_h2(p10.x, p10.y);
        hi.z = pack_h2(p01.x, p01.y);
        hi.w = pack_h2(p11.x, p11.y);
        *(uint4*)(smA + (mt * 16 + ks) * 512 + l16) = hi;
    }
    __syncthreads();                                   // B2: A1 ready

    // ---- GEMM1: 4 chunks x 4 ks, ring-streamed Wbi ----
    float C[2][8][4];
    #pragma unroll
    for (int m = 0; m < 2; m++)
        #pragma unroll
        for (int a = 0; a < 8; a++)
            #pragma unroll
            for (int b = 0; b < 4; b++) C[m][a][b] = 0.f;

    #pragma unroll
    for (int c = 0; c < 4; c++) {
        CPA_WAIT(1);
        __syncthreads();                               // chunk c visible
        const char* bb = smRing + (c & 1) * 16384;
        #pragma unroll
        for (int klc = 0; klc < 4; klc++)
            mma_step(smA, bb + klc * 4096, c * 4 + klc, mi, ni, l16, C);
        __syncthreads();                               // buf (c&1) reusable
        issue_chunk(sm_u32 + OFF_RING, c + 2, wbiP, w1P, tid);
    }

    // ---- epilogue1: ELU(C+bbi) -> fp16 -> A2 frag lines (ks 0..7) ----
    #pragma unroll
    for (int mtl = 0; mtl < 2; mtl++) {
        #pragma unroll
        for (int s = 0; s < 4; s++) {
            uint4 hi;
            int col = ni * 64 + (2 * s) * 8 + 2 * t;
            {
                const float bb0 = sBbi[col], bb1 = sBbi[col + 1];
                hi.x = pack_h2(eluf(C[mtl][2 * s][0] + bb0), eluf(C[mtl][2 * s][1] + bb1));
                hi.y = pack_h2(eluf(C[mtl][2 * s][2] + bb0), eluf(C[mtl][2 * s][3] + bb1));
            }
            col += 8;
            {
                const float bb0 = sBbi[col], bb1 = sBbi[col + 1];
                hi.z = pack_h2(eluf(C[mtl][2 * s + 1][0] + bb0), eluf(C[mtl][2 * s + 1][1] + bb1));
                hi.w = pack_h2(eluf(C[mtl][2 * s + 1][2] + bb0), eluf(C[mtl][2 * s + 1][3] + bb1));
            }
            const int mt2 = mi * 2 + mtl, ks2 = ni * 4 + s;
            *(uint4*)(smA + (mt2 * 16 + ks2) * 512 + l16) = hi;
        }
    }

    // ---- GEMM2: chunks 4,5 (W1), ks 0..7 ----
    float C2[2][8][4];
    #pragma unroll
    for (int m = 0; m < 2; m++)
        #pragma unroll
        for (int a = 0; a < 8; a++)
            #pragma unroll
            for (int b = 0; b < 4; b++) C2[m][a][b] = 0.f;

    CPA_WAIT(1);
    __syncthreads();                                   // chunk 4 + A2 visible
    {
        const char* bb = smRing + (4 & 1) * 16384;
        #pragma unroll
        for (int klc = 0; klc < 4; klc++)
            mma_step(smA, bb + klc * 4096, klc, mi, ni, l16, C2);
    }
    CPA_WAIT(0);
    __syncthreads();                                   // chunk 5 visible
    {
        const char* bb = smRing + (5 & 1) * 16384;
        #pragma unroll
        for (int klc = 0; klc < 4; klc++)
            mma_step(smA, bb + klc * 4096, 4 + klc, mi, ni, l16, C2);
    }

    // ---- epilogue2: ELU(C2+b1) . W2, quad-shuffle reduce, sigmoid ----
    #pragma unroll
    for (int mtl = 0; mtl < 2; mtl++) {
        float r0 = 0.f, r1 = 0.f;
        #pragma unroll
        for (int ntl = 0; ntl < 8; ntl++) {
            const int col = ni * 64 + ntl * 8 + 2 * t;
            const float w0 = sW2[col], w1 = sW2[col + 1];
            const float bb0 = sB1[col], bb1 = sB1[col + 1];
            r0 += eluf(C2[mtl][ntl][0] + bb0) * w0 + eluf(C2[mtl][ntl][1] + bb1) * w1;
            r1 += eluf(C2[mtl][ntl][2] + bb0) * w0 + eluf(C2[mtl][ntl][3] + bb1) * w1;
        }
        r0 += __shfl_xor_sync(0xffffffffu, r0, 1);
        r1 += __shfl_xor_sync(0xffffffffu, r1, 1);
        r0 += __shfl_xor_sync(0xffffffffu, r0, 2);
        r1 += __shfl_xor_sync(0xffffffffu, r1, 2);
        if (t == 0) {
            const int m = (mi * 2 + mtl) * 16 + g;
            sPart[ni * 128 + m]     = r0;
            sPart[ni * 128 + m + 8] = r1;
        }
    }
    __syncthreads();
    if (tid < 128) {
        const int ge = base + tid;
        if (ge < E) {
            float s = sPart[tid] + sPart[128 + tid] + b2v;
            out[(size_t)type * E + ge] = 1.f / (1.f + __expf(-s));
        }
    }
}

extern "C" void kernel_launch(void* const* d_in, const int* in_sizes, int n_in,
                              void* d_out, int out_size) {
    (void)n_in; (void)out_size;
    const int E = in_sizes[2] / 2;
    pack_weights_kernel<<<96, 512>>>(
        (const float*)d_in[4], (const float*)d_in[6],
        (const float*)d_in[10], (const float*)d_in[12]);
    cudaFuncSetAttribute(edge_decoder_mma,
                         cudaFuncAttributeMaxDynamicSharedMemorySize, SMEM_TOTAL);
    dim3 grid((E + 127) / 128, 2);
    edge_decoder_mma<<<grid, NTH, SMEM_TOTAL>>>(
        (const float*)d_in[0],  (const float*)d_in[1],
        d_in[2], d_in[3],
        (const float*)d_in[5],  (const float*)d_in[7],
        (const float*)d_in[8],  (const float*)d_in[9],
        (const float*)d_in[11], (const float*)d_in[13],
        (const float*)d_in[14], (const float*)d_in[15],
        (float*)d_out, E);
}